// round 1
// baseline (speedup 1.0000x reference)
#include <cuda_runtime.h>
#include <cuda_bf16.h>

#define V    50000
#define NNZ  1600000
#define Bb   4
#define FIN  128
#define FOUT 128
#define KK   5
#define F    (FIN * Bb)   // 512

// ---------------- scratch (static device arrays; no allocation) ----------------
__device__ float g_x[KK][V * F];          // Chebyshev terms, layout [v][b][fin]
__device__ int   g_colsS[NNZ];
__device__ float g_valsS[NNZ];
__device__ int   g_rowstart[V + 1];
__device__ int   g_cnt[V];
__device__ float g_W2[KK * FIN][FOUT];    // W2[k*128+fin][fo] = Wraw[(fin*5+k)*128+fo]

// ---------------- CSR build ----------------
__global__ void zero_cnt_kernel() {
    int i = blockIdx.x * blockDim.x + threadIdx.x;
    if (i < V) g_cnt[i] = 0;
}

__global__ void count_kernel(const int* __restrict__ rows) {
    int i = blockIdx.x * blockDim.x + threadIdx.x;
    if (i < NNZ) atomicAdd(&g_cnt[rows[i]], 1);
}

// single-block exclusive scan over g_cnt -> g_rowstart; also re-zeros g_cnt for scatter cursors
__global__ void scan_kernel() {
    __shared__ int s[1024];
    int tid = threadIdx.x;
    int carry = 0;
    for (int base = 0; base < V; base += 1024) {
        int i = base + tid;
        int x = 0;
        if (i < V) { x = g_cnt[i]; g_cnt[i] = 0; }
        s[tid] = x;
        __syncthreads();
        for (int off = 1; off < 1024; off <<= 1) {
            int t = (tid >= off) ? s[tid - off] : 0;
            __syncthreads();
            s[tid] += t;
            __syncthreads();
        }
        if (i < V) g_rowstart[i] = carry + s[tid] - x;  // exclusive
        carry += s[1023];
        __syncthreads();
    }
    if (tid == 0) g_rowstart[V] = carry;
}

__global__ void scatter_kernel(const int* __restrict__ rows,
                               const int* __restrict__ cols,
                               const float* __restrict__ vals) {
    int i = blockIdx.x * blockDim.x + threadIdx.x;
    if (i < NNZ) {
        int r = rows[i];
        int p = g_rowstart[r] + atomicAdd(&g_cnt[r], 1);
        g_colsS[p] = cols[i];
        g_valsS[p] = vals[i];
    }
}

// ---------------- weight permutation ----------------
__global__ void repack_w_kernel(const float* __restrict__ w) {
    int kk = blockIdx.x;          // 0..639 = kb*128 + fin
    int t  = threadIdx.x;         // fo
    int kb = kk >> 7;
    int fin = kk & 127;
    g_W2[kk][t] = w[(fin * KK + kb) * FOUT + t];
}

// ---------------- input transpose: inputs[b][v][fin] -> g_x[0][v][b][fin] ----------------
__global__ void transpose_kernel(const float* __restrict__ inp) {
    int v = blockIdx.x, b = blockIdx.y, t = threadIdx.x;
    g_x[0][(v * Bb + b) * FIN + t] = inp[((long)b * V + v) * FIN + t];
}

// ---------------- CSR SpMM: g_x[kout] = alpha * L @ g_x[kin] - g_x[ksub] ----------------
__global__ __launch_bounds__(F) void spmm_kernel(int kin, int ksub, int kout, float alpha) {
    int v = blockIdx.x;
    int t = threadIdx.x;
    const float* __restrict__ xin = g_x[kin];
    int s = g_rowstart[v];
    int e = g_rowstart[v + 1];
    float acc0 = 0.f, acc1 = 0.f;
    int i = s;
    for (; i + 2 <= e; i += 2) {
        int   c0 = g_colsS[i],  c1 = g_colsS[i + 1];
        float w0 = g_valsS[i],  w1 = g_valsS[i + 1];
        acc0 += w0 * xin[c0 * F + t];
        acc1 += w1 * xin[c1 * F + t];
    }
    if (i < e) acc0 += g_valsS[i] * xin[g_colsS[i] * F + t];
    float r = alpha * (acc0 + acc1);
    if (ksub >= 0) r -= g_x[ksub][v * F + t];
    g_x[kout][v * F + t] = r;
}

// ---------------- GEMM: out[m][fo] = sum_{kb,fin} A[m][kb*128+fin]*W2[kb*128+fin][fo] + bias ----------------
// A[m][kb*128+fin] = g_x[kb][(v*Bb+b)*FIN+fin], m = b*V+v. Uses fma.rn.f32x2 (2x fp32 rate).
#define BM 128
#define BN 128
#define BKT 16

__global__ __launch_bounds__(256) void gemm_kernel(const float* __restrict__ bias,
                                                   float* __restrict__ out) {
    __shared__ float As[BKT][BM];
    __shared__ float Bs[BKT][BN];
    int tid = threadIdx.x;
    int m0 = blockIdx.x * BM;
    int tx = tid & 15, ty = tid >> 4;

    // A load mapping: row = tid>>1 (0..127), col group = (tid&1)*8
    int ar = tid >> 1;
    int ac = (tid & 1) * 8;
    int am = m0 + ar;
    bool avalid = am < (Bb * V);
    int abase = 0;
    if (avalid) {
        int b = am / V;
        int v = am - b * V;
        abase = (v * Bb + b) * FIN;
    }
    // B load mapping: row = tid>>4 (0..15), col = (tid&15)*8
    int br = tid >> 4;
    int bc = (tid & 15) * 8;

    unsigned long long acc[8][4];
#pragma unroll
    for (int i = 0; i < 8; ++i)
#pragma unroll
        for (int j = 0; j < 4; ++j) acc[i][j] = 0ull;

    for (int kt = 0; kt < KK * FIN; kt += BKT) {
        int kb = kt >> 7;
        int f0 = kt & 127;
        float4 a0, a1;
        if (avalid) {
            const float4* p = reinterpret_cast<const float4*>(&g_x[kb][abase + f0 + ac]);
            a0 = p[0]; a1 = p[1];
        } else {
            a0 = make_float4(0.f, 0.f, 0.f, 0.f);
            a1 = a0;
        }
        const float4* q = reinterpret_cast<const float4*>(&g_W2[kt + br][bc]);
        float4 b0 = q[0], b1 = q[1];

        __syncthreads();
        As[ac + 0][ar] = a0.x; As[ac + 1][ar] = a0.y;
        As[ac + 2][ar] = a0.z; As[ac + 3][ar] = a0.w;
        As[ac + 4][ar] = a1.x; As[ac + 5][ar] = a1.y;
        As[ac + 6][ar] = a1.z; As[ac + 7][ar] = a1.w;
        *reinterpret_cast<float4*>(&Bs[br][bc])     = b0;
        *reinterpret_cast<float4*>(&Bs[br][bc + 4]) = b1;
        __syncthreads();

#pragma unroll
        for (int kq = 0; kq < BKT; ++kq) {
            float a[8];
            *reinterpret_cast<float4*>(&a[0]) = *reinterpret_cast<const float4*>(&As[kq][ty * 8]);
            *reinterpret_cast<float4*>(&a[4]) = *reinterpret_cast<const float4*>(&As[kq][ty * 8 + 4]);
            unsigned long long b2[4];
            const unsigned long long* bp =
                reinterpret_cast<const unsigned long long*>(&Bs[kq][tx * 8]);
            b2[0] = bp[0]; b2[1] = bp[1]; b2[2] = bp[2]; b2[3] = bp[3];
#pragma unroll
            for (int i = 0; i < 8; ++i) {
                unsigned long long a2;
                asm("mov.b64 %0, {%1, %2};" : "=l"(a2) : "f"(a[i]), "f"(a[i]));
#pragma unroll
                for (int j = 0; j < 4; ++j) {
                    asm("fma.rn.f32x2 %0, %1, %2, %0;"
                        : "+l"(acc[i][j]) : "l"(a2), "l"(b2[j]));
                }
            }
        }
    }

    // epilogue
#pragma unroll
    for (int i = 0; i < 8; ++i) {
        int m = m0 + ty * 8 + i;
        if (m < Bb * V) {
#pragma unroll
            for (int j = 0; j < 4; ++j) {
                float lo, hi;
                asm("mov.b64 {%0, %1}, %2;" : "=f"(lo), "=f"(hi) : "l"(acc[i][j]));
                int n = tx * 8 + j * 2;
                out[(long)m * FOUT + n]     = lo + bias[n];
                out[(long)m * FOUT + n + 1] = hi + bias[n + 1];
            }
        }
    }
}

// ---------------- launch ----------------
extern "C" void kernel_launch(void* const* d_in, const int* in_sizes, int n_in,
                              void* d_out, int out_size) {
    const int*   rows = (const int*)d_in[0];
    const int*   cols = (const int*)d_in[1];
    const float* vals = (const float*)d_in[2];
    const float* inp  = (const float*)d_in[3];
    const float* w    = (const float*)d_in[4];
    const float* bias = (const float*)d_in[5];
    float* out = (float*)d_out;

    zero_cnt_kernel<<<(V + 255) / 256, 256>>>();
    count_kernel<<<(NNZ + 255) / 256, 256>>>(rows);
    scan_kernel<<<1, 1024>>>();
    scatter_kernel<<<(NNZ + 255) / 256, 256>>>(rows, cols, vals);
    repack_w_kernel<<<KK * FIN, FOUT>>>(w);
    transpose_kernel<<<dim3(V, Bb), FIN>>>(inp);

    // Chebyshev recursion: x1 = L x0; xk = 2 L x_{k-1} - x_{k-2}
    spmm_kernel<<<V, F>>>(0, -1, 1, 1.0f);
    spmm_kernel<<<V, F>>>(1,  0, 2, 2.0f);
    spmm_kernel<<<V, F>>>(2,  1, 3, 2.0f);
    spmm_kernel<<<V, F>>>(3,  2, 4, 2.0f);

    gemm_kernel<<<(Bb * V + BM - 1) / BM, 256>>>(bias, out);
}

// round 11
// speedup vs baseline: 2.1611x; 2.1611x over previous
#include <cuda_runtime.h>
#include <cuda_fp16.h>
#include <cstdint>

#define V    50000
#define NNZ  1600000
#define Bb   4
#define FIN  128
#define FOUT 128
#define KK   5
#define F    (FIN * Bb)   // 512
#define M_TOT (Bb * V)    // 200000

// ---------------- scratch (static device arrays; no allocation) ----------------
__device__ __align__(256) float  g_x[KK][V * F];    // fp32 master, layout [v][b][fin]
__device__ __align__(256) __half g_xh[KK][V * F];   // fp16 shadow (gather + GEMM A)
__device__ int   g_colsS[NNZ];
__device__ float g_valsS[NNZ];
__device__ int   g_rowstart[V + 1];
__device__ int   g_cnt[V];
__device__ __align__(256) __half g_Wh[FOUT * KK * FIN]; // [n][k] K-major, k=kb*128+fin

// ---------------- helpers ----------------
__device__ __forceinline__ uint32_t smem_u32(const void* p) {
    uint32_t a;
    asm("{ .reg .u64 t; cvta.to.shared.u64 t, %1; cvt.u32.u64 %0, t; }" : "=r"(a) : "l"(p));
    return a;
}
__device__ __forceinline__ void cp16(uint32_t dst, const void* src) {
    asm volatile("cp.async.cg.shared.global [%0], [%1], 16;" :: "r"(dst), "l"(src));
}
__device__ __forceinline__ void ldmatrix_x4(uint32_t& r0, uint32_t& r1, uint32_t& r2,
                                            uint32_t& r3, uint32_t addr) {
    asm volatile("ldmatrix.sync.aligned.m8n8.x4.shared.b16 {%0,%1,%2,%3}, [%4];"
                 : "=r"(r0), "=r"(r1), "=r"(r2), "=r"(r3) : "r"(addr));
}
__device__ __forceinline__ void mma_16816(float& c0, float& c1, float& c2, float& c3,
                                          uint32_t a0, uint32_t a1, uint32_t a2, uint32_t a3,
                                          uint32_t b0, uint32_t b1) {
    asm volatile(
        "mma.sync.aligned.m16n8k16.row.col.f32.f16.f16.f32 "
        "{%0,%1,%2,%3}, {%4,%5,%6,%7}, {%8,%9}, {%0,%1,%2,%3};"
        : "+f"(c0), "+f"(c1), "+f"(c2), "+f"(c3)
        : "r"(a0), "r"(a1), "r"(a2), "r"(a3), "r"(b0), "r"(b1));
}

// ---------------- CSR build ----------------
__global__ void zero_cnt_kernel() {
    int i = blockIdx.x * blockDim.x + threadIdx.x;
    if (i < V) g_cnt[i] = 0;
}
__global__ void count_kernel(const int* __restrict__ rows) {
    int i = blockIdx.x * blockDim.x + threadIdx.x;
    if (i < NNZ) atomicAdd(&g_cnt[rows[i]], 1);
}
__global__ void scan_kernel() {
    __shared__ int s[1024];
    int tid = threadIdx.x;
    int carry = 0;
    for (int base = 0; base < V; base += 1024) {
        int i = base + tid;
        int x = 0;
        if (i < V) { x = g_cnt[i]; g_cnt[i] = 0; }
        s[tid] = x;
        __syncthreads();
        for (int off = 1; off < 1024; off <<= 1) {
            int t = (tid >= off) ? s[tid - off] : 0;
            __syncthreads();
            s[tid] += t;
            __syncthreads();
        }
        if (i < V) g_rowstart[i] = carry + s[tid] - x;
        carry += s[1023];
        __syncthreads();
    }
    if (tid == 0) g_rowstart[V] = carry;
}
__global__ void scatter_kernel(const int* __restrict__ rows,
                               const int* __restrict__ cols,
                               const float* __restrict__ vals) {
    int i = blockIdx.x * blockDim.x + threadIdx.x;
    if (i < NNZ) {
        int r = rows[i];
        int p = g_rowstart[r] + atomicAdd(&g_cnt[r], 1);
        g_colsS[p] = cols[i];
        g_valsS[p] = vals[i];
    }
}

// ---------------- weight repack: g_Wh[n][kb*128+fin] = Wraw[(fin*5+kb)*128+n] (fp16) ---
__global__ void repack_w_kernel(const float* __restrict__ w) {
    int kk = blockIdx.x;          // kb*128 + fin
    int n  = threadIdx.x;
    int kb = kk >> 7;
    int fin = kk & 127;
    g_Wh[n * (KK * FIN) + kk] = __float2half(w[(fin * KK + kb) * FOUT + n]);
}

// ---------------- transpose: inputs[b][v][fin] -> x0[v][b][fin] (fp32 + fp16) ----------
__global__ void transpose_kernel(const float* __restrict__ inp) {
    int v = blockIdx.x, b = blockIdx.y, t = threadIdx.x;
    float val = inp[((long)b * V + v) * FIN + t];
    int o = (v * Bb + b) * FIN + t;
    g_x[0][o] = val;
    g_xh[0][o] = __float2half(val);
}

// ---------------- SpMM (fp16 gather, fp32 accum/master): x[kout] = a*L@x[kin] - x[ksub]
__global__ __launch_bounds__(256) void spmm_kernel(int kin, int ksub, int kout, float alpha) {
    int v = blockIdx.x;
    int t = threadIdx.x;   // handles features 2t, 2t+1
    const __half2* __restrict__ xin = (const __half2*)g_xh[kin];
    const int*   __restrict__ colp = g_colsS;
    const float* __restrict__ valp = g_valsS;
    int s = g_rowstart[v];
    int e = g_rowstart[v + 1];
    float ax0 = 0.f, ay0 = 0.f, ax1 = 0.f, ay1 = 0.f;
    int i = s;
    for (; i + 2 <= e; i += 2) {
        int   c0 = colp[i],     c1 = colp[i + 1];
        float w0 = valp[i],     w1 = valp[i + 1];
        float2 f0 = __half22float2(xin[c0 * (F / 2) + t]);
        float2 f1 = __half22float2(xin[c1 * (F / 2) + t]);
        ax0 += w0 * f0.x; ay0 += w0 * f0.y;
        ax1 += w1 * f1.x; ay1 += w1 * f1.y;
    }
    if (i < e) {
        int c = colp[i]; float w = valp[i];
        float2 f = __half22float2(xin[c * (F / 2) + t]);
        ax0 += w * f.x; ay0 += w * f.y;
    }
    float rx = alpha * (ax0 + ax1);
    float ry = alpha * (ay0 + ay1);
    int o = v * (F / 2) + t;
    if (ksub >= 0) {
        float2 p = ((const float2*)g_x[ksub])[o];
        rx -= p.x; ry -= p.y;
    }
    ((float2*)g_x[kout])[o] = make_float2(rx, ry);
    ((__half2*)g_xh[kout])[o] = __floats2half2_rn(rx, ry);
}

// ---------------- HMMA GEMM: out[m][n] = sum_k A[m][k] * Wh[n][k] + bias ----------------
// A[m][kb*128+fin] = g_xh[kb][(v*4+b)*128+fin], m = b*V+v. K=640 in 10 chunks of 64 halves.
// Block: 128x128 tile, 256 threads (8 warps, 64x32 warp tiles). Double-buffered cp.async.
#define BK      64
#define ASTRH   72                       // padded row stride in halves (144B)
#define TILE_B  (128 * ASTRH * 2)        // 18432 bytes per operand tile
#define BUF_B   (2 * TILE_B)             // A + W per buffer
#define SMEM_DYN (2 * BUF_B)             // 73728 bytes

__global__ __launch_bounds__(256) void gemm_hmma_kernel(const float* __restrict__ bias,
                                                        float* __restrict__ out) {
    extern __shared__ char smem[];
    uint32_t sb = smem_u32(smem);
    int tid = threadIdx.x;
    int lane = tid & 31, wid = tid >> 5;
    int wm = wid & 1, wn = wid >> 1;     // warp grid 2 (M) x 4 (N)
    int m0 = blockIdx.x * 128;

    // ---- load mapping: thread covers 64B (4 x 16B) of one 128B row; 2 threads/row ----
    int lrow = tid >> 1;                  // 0..127
    int lseg = (tid & 1) * 4;             // starting 16B segment
    int am = m0 + lrow;
    if (am >= M_TOT) am = M_TOT - 1;      // clamp (results guarded at store)
    int b = am / V;
    int v = am - b * V;
    int arow = (v * Bb + b) * FIN;        // half offset into g_xh[kb]

    uint32_t a_dst_base = sb + lrow * (ASTRH * 2) + lseg * 16;
    uint32_t w_dst_base = a_dst_base + TILE_B;
    const __half* wsrc_row = &g_Wh[lrow * (KK * FIN)];

    auto issue = [&](int c) {
        int kb = c >> 1;
        const __half* as = &g_xh[kb][arow + (c & 1) * BK + lseg * 8];
        const __half* ws = wsrc_row + c * BK + lseg * 8;
        uint32_t base = (c & 1) * BUF_B;
#pragma unroll
        for (int i = 0; i < 4; ++i) {
            cp16(a_dst_base + base + i * 16, as + i * 8);
            cp16(w_dst_base + base + i * 16, ws + i * 8);
        }
        asm volatile("cp.async.commit_group;" ::: "memory");
    };

    float acc[4][4][4];                   // [mi][ni][reg]
#pragma unroll
    for (int mi = 0; mi < 4; ++mi)
#pragma unroll
        for (int ni = 0; ni < 4; ++ni)
#pragma unroll
            for (int r = 0; r < 4; ++r) acc[mi][ni][r] = 0.f;

    issue(0);
    issue(1);

    // per-lane ldmatrix address pieces (A): row = Rbase + (lane&15), col = ks*16 + (lane>>4)*8
    int a_lrow = lane & 15;
    int a_lcol = (lane >> 4) << 3;
    // B direct-load pieces: n = base + lane>>2, k = ks*16 + (lane&3)*2
    int b_ln = lane >> 2;
    int b_lk = (lane & 3) * 2;

    for (int c = 0; c < 10; ++c) {
        if (c == 9) asm volatile("cp.async.wait_group 0;" ::: "memory");
        else        asm volatile("cp.async.wait_group 1;" ::: "memory");
        __syncthreads();

        uint32_t abase = sb + (c & 1) * BUF_B;
#pragma unroll
        for (int ks = 0; ks < 4; ++ks) {
            uint32_t a[4][4];
#pragma unroll
            for (int mi = 0; mi < 4; ++mi) {
                int row = wm * 64 + mi * 16 + a_lrow;
                int col = ks * 16 + a_lcol;
                ldmatrix_x4(a[mi][0], a[mi][1], a[mi][2], a[mi][3],
                            abase + row * (ASTRH * 2) + col * 2);
            }
            uint32_t bfr[4][2];
#pragma unroll
            for (int ni = 0; ni < 4; ++ni) {
                int n = wn * 32 + ni * 8 + b_ln;
                const __half* bp = (const __half*)(smem + (c & 1) * BUF_B + TILE_B) +
                                   n * ASTRH + ks * 16 + b_lk;
                bfr[ni][0] = *(const uint32_t*)bp;
                bfr[ni][1] = *(const uint32_t*)(bp + 8);
            }
#pragma unroll
            for (int mi = 0; mi < 4; ++mi)
#pragma unroll
                for (int ni = 0; ni < 4; ++ni)
                    mma_16816(acc[mi][ni][0], acc[mi][ni][1], acc[mi][ni][2], acc[mi][ni][3],
                              a[mi][0], a[mi][1], a[mi][2], a[mi][3],
                              bfr[ni][0], bfr[ni][1]);
        }
        __syncthreads();
        if (c + 2 < 10) issue(c + 2);
    }

    // ---- epilogue: d0,d1 -> row lane>>2, cols +0,+1 ; d2,d3 -> row+8 ----
#pragma unroll
    for (int mi = 0; mi < 4; ++mi) {
        int r0 = m0 + wm * 64 + mi * 16 + (lane >> 2);
        int r1 = r0 + 8;
#pragma unroll
        for (int ni = 0; ni < 4; ++ni) {
            int col = wn * 32 + ni * 8 + (lane & 3) * 2;
            float bx = bias[col], by = bias[col + 1];
            if (r0 < M_TOT)
                *(float2*)&out[(long)r0 * FOUT + col] =
                    make_float2(acc[mi][ni][0] + bx, acc[mi][ni][1] + by);
            if (r1 < M_TOT)
                *(float2*)&out[(long)r1 * FOUT + col] =
                    make_float2(acc[mi][ni][2] + bx, acc[mi][ni][3] + by);
        }
    }
}

// ---------------- launch ----------------
extern "C" void kernel_launch(void* const* d_in, const int* in_sizes, int n_in,
                              void* d_out, int out_size) {
    const int*   rows = (const int*)d_in[0];
    const int*   cols = (const int*)d_in[1];
    const float* vals = (const float*)d_in[2];
    const float* inp  = (const float*)d_in[3];
    const float* w    = (const float*)d_in[4];
    const float* bias = (const float*)d_in[5];
    float* out = (float*)d_out;

    cudaFuncSetAttribute(gemm_hmma_kernel, cudaFuncAttributeMaxDynamicSharedMemorySize, SMEM_DYN);

    zero_cnt_kernel<<<(V + 255) / 256, 256>>>();
    count_kernel<<<(NNZ + 255) / 256, 256>>>(rows);
    scan_kernel<<<1, 1024>>>();
    scatter_kernel<<<(NNZ + 255) / 256, 256>>>(rows, cols, vals);
    repack_w_kernel<<<KK * FIN, FOUT>>>(w);
    transpose_kernel<<<dim3(V, Bb), FIN>>>(inp);

    spmm_kernel<<<V, 256>>>(0, -1, 1, 1.0f);
    spmm_kernel<<<V, 256>>>(1,  0, 2, 2.0f);
    spmm_kernel<<<V, 256>>>(2,  1, 3, 2.0f);
    spmm_kernel<<<V, 256>>>(3,  2, 4, 2.0f);

    gemm_hmma_kernel<<<(M_TOT + 127) / 128, 256, SMEM_DYN>>>(bias, out);
}

// round 12
// speedup vs baseline: 2.3378x; 1.0818x over previous
#include <cuda_runtime.h>
#include <cuda_fp16.h>
#include <cstdint>

#define V    50000
#define NNZ  1600000
#define Bb   4
#define FIN  128
#define FOUT 128
#define KK   5
#define F    (FIN * Bb)   // 512
#define M_TOT (Bb * V)    // 200000

// ---------------- scratch (static device arrays; no allocation) ----------------
__device__ __align__(256) __half g_xh[KK][V * F];   // fp16 Chebyshev terms [v][b][fin]
__device__ int   g_colsS[NNZ];
__device__ float g_valsS[NNZ];
__device__ int   g_rowstart[V + 1];
__device__ int   g_cnt[V];
__device__ __align__(256) __half g_Wh[FOUT * KK * FIN]; // [n][k] K-major, k=kb*128+fin

// ---------------- helpers ----------------
__device__ __forceinline__ uint32_t smem_u32(const void* p) {
    uint32_t a;
    asm("{ .reg .u64 t; cvta.to.shared.u64 t, %1; cvt.u32.u64 %0, t; }" : "=r"(a) : "l"(p));
    return a;
}
__device__ __forceinline__ void cp16(uint32_t dst, const void* src) {
    asm volatile("cp.async.cg.shared.global [%0], [%1], 16;" :: "r"(dst), "l"(src));
}
__device__ __forceinline__ void ldmatrix_x4(uint32_t& r0, uint32_t& r1, uint32_t& r2,
                                            uint32_t& r3, uint32_t addr) {
    asm volatile("ldmatrix.sync.aligned.m8n8.x4.shared.b16 {%0,%1,%2,%3}, [%4];"
                 : "=r"(r0), "=r"(r1), "=r"(r2), "=r"(r3) : "r"(addr));
}
__device__ __forceinline__ void mma_16816(float& c0, float& c1, float& c2, float& c3,
                                          uint32_t a0, uint32_t a1, uint32_t a2, uint32_t a3,
                                          uint32_t b0, uint32_t b1) {
    asm volatile(
        "mma.sync.aligned.m16n8k16.row.col.f32.f16.f16.f32 "
        "{%0,%1,%2,%3}, {%4,%5,%6,%7}, {%8,%9}, {%0,%1,%2,%3};"
        : "+f"(c0), "+f"(c1), "+f"(c2), "+f"(c3)
        : "r"(a0), "r"(a1), "r"(a2), "r"(a3), "r"(b0), "r"(b1));
}

// ---------------- CSR build ----------------
__global__ void zero_cnt_kernel() {
    int i = blockIdx.x * blockDim.x + threadIdx.x;
    if (i < V) g_cnt[i] = 0;
}
__global__ void count_kernel(const int* __restrict__ rows) {
    int i = blockIdx.x * blockDim.x + threadIdx.x;
    if (i < NNZ) atomicAdd(&g_cnt[rows[i]], 1);
}
// single-block exclusive scan (warp-shuffle based), re-zeros g_cnt
__global__ __launch_bounds__(1024) void scan_kernel() {
    __shared__ int warp_sums[32];
    int tid = threadIdx.x;
    int lane = tid & 31, w = tid >> 5;
    int carry = 0;
    for (int base = 0; base < V; base += 1024) {
        int i = base + tid;
        int x = 0;
        if (i < V) { x = g_cnt[i]; g_cnt[i] = 0; }
        int v = x;
#pragma unroll
        for (int off = 1; off < 32; off <<= 1) {
            int t = __shfl_up_sync(0xFFFFFFFFu, v, off);
            if (lane >= off) v += t;
        }
        if (lane == 31) warp_sums[w] = v;
        __syncthreads();
        if (w == 0) {
            int s = warp_sums[lane];
#pragma unroll
            for (int off = 1; off < 32; off <<= 1) {
                int t = __shfl_up_sync(0xFFFFFFFFu, s, off);
                if (lane >= off) s += t;
            }
            warp_sums[lane] = s;
        }
        __syncthreads();
        int wbase = (w > 0) ? warp_sums[w - 1] : 0;
        if (i < V) g_rowstart[i] = carry + wbase + v - x;   // exclusive
        carry += warp_sums[31];
        __syncthreads();
    }
    if (tid == 0) g_rowstart[V] = carry;
}
__global__ void scatter_kernel(const int* __restrict__ rows,
                               const int* __restrict__ cols,
                               const float* __restrict__ vals) {
    int i = blockIdx.x * blockDim.x + threadIdx.x;
    if (i < NNZ) {
        int r = rows[i];
        int p = g_rowstart[r] + atomicAdd(&g_cnt[r], 1);
        g_colsS[p] = cols[i];
        g_valsS[p] = vals[i];
    }
}

// ---------------- weight repack: g_Wh[n][kb*128+fin] = Wraw[(fin*5+kb)*128+n] (fp16) ---
__global__ void repack_w_kernel(const float* __restrict__ w) {
    int kk = blockIdx.x;          // kb*128 + fin
    int n  = threadIdx.x;
    int kb = kk >> 7;
    int fin = kk & 127;
    g_Wh[n * (KK * FIN) + kk] = __float2half(w[(fin * KK + kb) * FOUT + n]);
}

// ---------------- transpose: inputs[b][v][fin] -> x0[v][b][fin] (fp16 only) ------------
__global__ void transpose_kernel(const float* __restrict__ inp) {
    int v = blockIdx.x, b = blockIdx.y, t = threadIdx.x;
    float val = inp[((long)b * V + v) * FIN + t];
    g_xh[0][(v * Bb + b) * FIN + t] = __float2half(val);
}

// ---------------- SpMM (fp16 gather/store, fp32 accum): x[kout] = a*L@x[kin] - x[ksub]
__global__ __launch_bounds__(256) void spmm_kernel(int kin, int ksub, int kout, float alpha) {
    int v = blockIdx.x;
    int t = threadIdx.x;   // handles features 2t, 2t+1
    const __half2* __restrict__ xin = (const __half2*)g_xh[kin];
    const int*   __restrict__ colp = g_colsS;
    const float* __restrict__ valp = g_valsS;
    int s = g_rowstart[v];
    int e = g_rowstart[v + 1];
    float ax0 = 0.f, ay0 = 0.f, ax1 = 0.f, ay1 = 0.f;
    int i = s;
    for (; i + 2 <= e; i += 2) {
        int   c0 = colp[i],     c1 = colp[i + 1];
        float w0 = valp[i],     w1 = valp[i + 1];
        float2 f0 = __half22float2(xin[c0 * (F / 2) + t]);
        float2 f1 = __half22float2(xin[c1 * (F / 2) + t]);
        ax0 += w0 * f0.x; ay0 += w0 * f0.y;
        ax1 += w1 * f1.x; ay1 += w1 * f1.y;
    }
    if (i < e) {
        int c = colp[i]; float w = valp[i];
        float2 f = __half22float2(xin[c * (F / 2) + t]);
        ax0 += w * f.x; ay0 += w * f.y;
    }
    float rx = alpha * (ax0 + ax1);
    float ry = alpha * (ay0 + ay1);
    int o = v * (F / 2) + t;
    if (ksub >= 0) {
        float2 p = __half22float2(((const __half2*)g_xh[ksub])[o]);
        rx -= p.x; ry -= p.y;
    }
    ((__half2*)g_xh[kout])[o] = __floats2half2_rn(rx, ry);
}

// ---------------- HMMA GEMM: out[m][n] = sum_k A[m][k] * Wh[n][k] + bias ----------------
// A[m][kb*128+fin] = g_xh[kb][(v*4+b)*128+fin], m = b*V+v. K=640 in 10 chunks of 64 halves.
// Block: 128x128 tile, 256 threads (8 warps, 64x32 warp tiles). Double-buffered cp.async.
#define BK      64
#define ASTRH   72                       // padded row stride in halves (144B)
#define TILE_B  (128 * ASTRH * 2)        // 18432 bytes per operand tile
#define BUF_B   (2 * TILE_B)             // A + W per buffer
#define SMEM_DYN (2 * BUF_B)             // 73728 bytes

__global__ __launch_bounds__(256) void gemm_hmma_kernel(const float* __restrict__ bias,
                                                        float* __restrict__ out) {
    extern __shared__ char smem[];
    uint32_t sb = smem_u32(smem);
    int tid = threadIdx.x;
    int lane = tid & 31, wid = tid >> 5;
    int wm = wid & 1, wn = wid >> 1;     // warp grid 2 (M) x 4 (N)
    int m0 = blockIdx.x * 128;

    // ---- load mapping: thread covers 64B (4 x 16B) of one 128B row; 2 threads/row ----
    int lrow = tid >> 1;                  // 0..127
    int lseg = (tid & 1) * 4;             // starting 16B segment
    int am = m0 + lrow;
    if (am >= M_TOT) am = M_TOT - 1;      // clamp (results guarded at store)
    int b = am / V;
    int v = am - b * V;
    int arow = (v * Bb + b) * FIN;        // half offset into g_xh[kb]

    uint32_t a_dst_base = sb + lrow * (ASTRH * 2) + lseg * 16;
    uint32_t w_dst_base = a_dst_base + TILE_B;
    const __half* wsrc_row = &g_Wh[lrow * (KK * FIN)];

    auto issue = [&](int c) {
        int kb = c >> 1;
        const __half* as = &g_xh[kb][arow + (c & 1) * BK + lseg * 8];
        const __half* ws = wsrc_row + c * BK + lseg * 8;
        uint32_t base = (c & 1) * BUF_B;
#pragma unroll
        for (int i = 0; i < 4; ++i) {
            cp16(a_dst_base + base + i * 16, as + i * 8);
            cp16(w_dst_base + base + i * 16, ws + i * 8);
        }
        asm volatile("cp.async.commit_group;" ::: "memory");
    };

    float acc[4][4][4];                   // [mi][ni][reg]
#pragma unroll
    for (int mi = 0; mi < 4; ++mi)
#pragma unroll
        for (int ni = 0; ni < 4; ++ni)
#pragma unroll
            for (int r = 0; r < 4; ++r) acc[mi][ni][r] = 0.f;

    issue(0);
    issue(1);

    // per-lane ldmatrix address pieces (A): row = Rbase + (lane&15), col = ks*16 + (lane>>4)*8
    int a_lrow = lane & 15;
    int a_lcol = (lane >> 4) << 3;
    // B direct-load pieces: n = base + lane>>2, k = ks*16 + (lane&3)*2
    int b_ln = lane >> 2;
    int b_lk = (lane & 3) * 2;

    for (int c = 0; c < 10; ++c) {
        if (c == 9) asm volatile("cp.async.wait_group 0;" ::: "memory");
        else        asm volatile("cp.async.wait_group 1;" ::: "memory");
        __syncthreads();

        uint32_t abase = sb + (c & 1) * BUF_B;
#pragma unroll
        for (int ks = 0; ks < 4; ++ks) {
            uint32_t a[4][4];
#pragma unroll
            for (int mi = 0; mi < 4; ++mi) {
                int row = wm * 64 + mi * 16 + a_lrow;
                int col = ks * 16 + a_lcol;
                ldmatrix_x4(a[mi][0], a[mi][1], a[mi][2], a[mi][3],
                            abase + row * (ASTRH * 2) + col * 2);
            }
            uint32_t bfr[4][2];
#pragma unroll
            for (int ni = 0; ni < 4; ++ni) {
                int n = wn * 32 + ni * 8 + b_ln;
                const __half* bp = (const __half*)(smem + (c & 1) * BUF_B + TILE_B) +
                                   n * ASTRH + ks * 16 + b_lk;
                bfr[ni][0] = *(const uint32_t*)bp;
                bfr[ni][1] = *(const uint32_t*)(bp + 8);
            }
#pragma unroll
            for (int mi = 0; mi < 4; ++mi)
#pragma unroll
                for (int ni = 0; ni < 4; ++ni)
                    mma_16816(acc[mi][ni][0], acc[mi][ni][1], acc[mi][ni][2], acc[mi][ni][3],
                              a[mi][0], a[mi][1], a[mi][2], a[mi][3],
                              bfr[ni][0], bfr[ni][1]);
        }
        __syncthreads();
        if (c + 2 < 10) issue(c + 2);
    }

    // ---- epilogue: d0,d1 -> row lane>>2, cols +0,+1 ; d2,d3 -> row+8 ----
#pragma unroll
    for (int mi = 0; mi < 4; ++mi) {
        int r0 = m0 + wm * 64 + mi * 16 + (lane >> 2);
        int r1 = r0 + 8;
#pragma unroll
        for (int ni = 0; ni < 4; ++ni) {
            int col = wn * 32 + ni * 8 + (lane & 3) * 2;
            float bx = bias[col], by = bias[col + 1];
            if (r0 < M_TOT)
                *(float2*)&out[(long)r0 * FOUT + col] =
                    make_float2(acc[mi][ni][0] + bx, acc[mi][ni][1] + by);
            if (r1 < M_TOT)
                *(float2*)&out[(long)r1 * FOUT + col] =
                    make_float2(acc[mi][ni][2] + bx, acc[mi][ni][3] + by);
        }
    }
}

// ---------------- launch ----------------
extern "C" void kernel_launch(void* const* d_in, const int* in_sizes, int n_in,
                              void* d_out, int out_size) {
    const int*   rows = (const int*)d_in[0];
    const int*   cols = (const int*)d_in[1];
    const float* vals = (const float*)d_in[2];
    const float* inp  = (const float*)d_in[3];
    const float* w    = (const float*)d_in[4];
    const float* bias = (const float*)d_in[5];
    float* out = (float*)d_out;

    cudaFuncSetAttribute(gemm_hmma_kernel, cudaFuncAttributeMaxDynamicSharedMemorySize, SMEM_DYN);

    zero_cnt_kernel<<<(V + 255) / 256, 256>>>();
    count_kernel<<<(NNZ + 255) / 256, 256>>>(rows);
    scan_kernel<<<1, 1024>>>();
    scatter_kernel<<<(NNZ + 255) / 256, 256>>>(rows, cols, vals);
    repack_w_kernel<<<KK * FIN, FOUT>>>(w);
    transpose_kernel<<<dim3(V, Bb), FIN>>>(inp);

    spmm_kernel<<<V, 256>>>(0, -1, 1, 1.0f);
    spmm_kernel<<<V, 256>>>(1,  0, 2, 2.0f);
    spmm_kernel<<<V, 256>>>(2,  1, 3, 2.0f);
    spmm_kernel<<<V, 256>>>(3,  2, 4, 2.0f);

    gemm_hmma_kernel<<<(M_TOT + 127) / 128, 256, SMEM_DYN>>>(bias, out);
}